// round 15
// baseline (speedup 1.0000x reference)
#include <cuda_runtime.h>
#include <cstdint>

// N=100000 candidates, OBS=16, FEAT=96 -> ROW=1536 floats per candidate.
// target_vels row = 25*96 = 2400 floats.
#define ROW_F       1536
#define ROW_F4      (ROW_F / 4)       // 384 float4
#define F4_PER_LANE (ROW_F4 / 32)     // 12
#define OUT_F       2400
#define OUT_F4      (OUT_F / 4)       // 600
#define WARPS_PER_BLOCK 8

// Statically initialized for the first (uncaptured) correctness call; the
// gather kernel (last in dependency order) resets it after use, so every
// graph replay starts clean.
__device__ unsigned long long g_best = 0xFFFFFFFFFFFFFFFFULL;

// FINAL floor configuration (best measured: 90.62us; population 90.6-90.9).
// One warp per candidate, 8 warps/block, shared-staged query (LDS rides the
// smem port -> exactly one LDG per loop iteration), 32 regs, ~97% occupancy.
// The 614 MB train stream runs at ~6.9 TB/s (~87% of HBM spec) — the hardware
// read ceiling for this pattern. Measured-neutral alternatives: LDG.256,
// __ldcs, 2 cands/warp, persistent grid, 128-thr blocks, global-resident
// query, fused epilogue. Traffic is irreducible for an exact argmin.
__global__ __launch_bounds__(256, 8) void nn_dist_kernel(
    const float* __restrict__ in_pose,
    const float* __restrict__ train,
    int N)
{
    __shared__ float4 s_q[ROW_F4];
    __shared__ unsigned long long s_best[WARPS_PER_BLOCK];

    const int tid  = threadIdx.x;
    const int warp = tid >> 5;
    const int lane = tid & 31;

    // stage query (6 KB) into shared
    for (int i = tid; i < ROW_F4; i += blockDim.x)
        s_q[i] = reinterpret_cast<const float4*>(in_pose)[i];
    __syncthreads();

    const int cand = blockIdx.x * WARPS_PER_BLOCK + warp;
    unsigned long long packed = 0xFFFFFFFFFFFFFFFFULL;

    if (cand < N) {
        const float4* row = reinterpret_cast<const float4*>(train) + (size_t)cand * ROW_F4;
        float acc = 0.f;
        #pragma unroll
        for (int j = 0; j < F4_PER_LANE; j++) {
            const int idx = j * 32 + lane;
            float4 a = row[idx];
            float4 q = s_q[idx];
            float dx = a.x - q.x;
            float dy = a.y - q.y;
            float dz = a.z - q.z;
            float dw = a.w - q.w;
            acc += dx * dx + dy * dy + dz * dz + dw * dw;
        }
        #pragma unroll
        for (int o = 16; o > 0; o >>= 1)
            acc += __shfl_xor_sync(0xFFFFFFFFu, acc, o);
        // acc >= 0 -> IEEE bits order-preserving; low 32 = index, so u64 min
        // ties break to the SMALLEST index (jnp.argmin first-min semantics).
        packed = ((unsigned long long)__float_as_uint(acc) << 32) | (unsigned)cand;
    }

    if (lane == 0) s_best[warp] = packed;
    __syncthreads();

    if (tid == 0) {
        unsigned long long b = s_best[0];
        #pragma unroll
        for (int w = 1; w < WARPS_PER_BLOCK; w++) b = min(b, s_best[w]);
        atomicMin(&g_best, b);
    }
    // Signal PDL: this block's contribution to g_best is committed.
    cudaTriggerProgrammaticLaunchCompletion();
}

// Launched with programmatic dependency: resident during the dist kernel,
// proceeds the instant all dist blocks have triggered (atomicMins visible
// per the PDL memory-visibility contract).
__global__ void nn_gather_kernel(const float* __restrict__ target_vels,
                                 float* __restrict__ out)
{
    cudaGridDependencySynchronize();

    __shared__ unsigned int s_bestidx;
    if (threadIdx.x == 0)
        s_bestidx = (unsigned)(g_best & 0xFFFFFFFFULL);
    __syncthreads();

    const float4* src = reinterpret_cast<const float4*>(target_vels)
                        + (size_t)s_bestidx * OUT_F4;
    float4* dst = reinterpret_cast<float4*>(out);
    for (int i = threadIdx.x; i < OUT_F4; i += blockDim.x)
        dst[i] = src[i];

    __syncthreads();
    if (threadIdx.x == 0)
        g_best = 0xFFFFFFFFFFFFFFFFULL;   // clean state for next replay
}

extern "C" void kernel_launch(void* const* d_in, const int* in_sizes, int n_in,
                              void* d_out, int out_size)
{
    const float* in_pose     = (const float*)d_in[0];   // [16, 96]
    const float* train_poses = (const float*)d_in[1];   // [N, 16, 96]
    const float* target_vels = (const float*)d_in[2];   // [N, 25, 96]
    float* out = (float*)d_out;                          // [25, 96]

    const int N = in_sizes[1] / ROW_F;
    const int blocks = (N + WARPS_PER_BLOCK - 1) / WARPS_PER_BLOCK;

    nn_dist_kernel<<<blocks, 256>>>(in_pose, train_poses, N);

    // Gather with programmatic dependent launch: overlaps launch/prologue
    // with the dist kernel; self-synchronizes via gridDependencySynchronize.
    cudaLaunchAttribute attrs[1];
    attrs[0].id = cudaLaunchAttributeProgrammaticStreamSerialization;
    attrs[0].val.programmaticStreamSerializationAllowed = 1;

    cudaLaunchConfig_t cfg = {};
    cfg.gridDim  = dim3(1, 1, 1);
    cfg.blockDim = dim3(256, 1, 1);
    cfg.dynamicSmemBytes = 0;
    cfg.stream = 0;
    cfg.attrs = attrs;
    cfg.numAttrs = 1;

    cudaLaunchKernelEx(&cfg, nn_gather_kernel, target_vels, out);
}

// round 16
// speedup vs baseline: 1.0014x; 1.0014x over previous
#include <cuda_runtime.h>
#include <cstdint>

// N=100000 candidates, OBS=16, FEAT=96 -> ROW=1536 floats per candidate.
// target_vels row = 25*96 = 2400 floats.
#define ROW_F       1536
#define ROW_F4      (ROW_F / 4)       // 384 float4
#define F4_PER_LANE (ROW_F4 / 32)     // 12
#define OUT_F       2400
#define OUT_F4      (OUT_F / 4)       // 600
#define WARPS_PER_BLOCK 8

// Statically initialized for the first (uncaptured) correctness call; the
// gather kernel (last in dependency order) resets it after use, so every
// graph replay starts clean.
__device__ unsigned long long g_best = 0xFFFFFFFFFFFFFFFFULL;

// CONVERGED floor configuration (measured population: 90.62/90.88/92.19/92.19;
// ±1.5us DVFS noise). One warp per candidate, 8 warps/block, shared-staged
// query (LDS rides the smem port -> exactly one LDG per loop iteration),
// 32 regs, ~97% occupancy. The 614 MB train stream runs at ~6.9 TB/s
// (~87% of HBM spec) — the hardware read ceiling for this pattern.
// Measured-neutral alternatives: LDG.256, __ldcs, 2 cands/warp, persistent
// grid, 128-thr blocks, global-resident query, fused epilogue. Traffic is
// irreducible for an exact argmin; PDL overlap (-2us) was the only real win.
__global__ __launch_bounds__(256, 8) void nn_dist_kernel(
    const float* __restrict__ in_pose,
    const float* __restrict__ train,
    int N)
{
    __shared__ float4 s_q[ROW_F4];
    __shared__ unsigned long long s_best[WARPS_PER_BLOCK];

    const int tid  = threadIdx.x;
    const int warp = tid >> 5;
    const int lane = tid & 31;

    // stage query (6 KB) into shared
    for (int i = tid; i < ROW_F4; i += blockDim.x)
        s_q[i] = reinterpret_cast<const float4*>(in_pose)[i];
    __syncthreads();

    const int cand = blockIdx.x * WARPS_PER_BLOCK + warp;
    unsigned long long packed = 0xFFFFFFFFFFFFFFFFULL;

    if (cand < N) {
        const float4* row = reinterpret_cast<const float4*>(train) + (size_t)cand * ROW_F4;
        float acc = 0.f;
        #pragma unroll
        for (int j = 0; j < F4_PER_LANE; j++) {
            const int idx = j * 32 + lane;
            float4 a = row[idx];
            float4 q = s_q[idx];
            float dx = a.x - q.x;
            float dy = a.y - q.y;
            float dz = a.z - q.z;
            float dw = a.w - q.w;
            acc += dx * dx + dy * dy + dz * dz + dw * dw;
        }
        #pragma unroll
        for (int o = 16; o > 0; o >>= 1)
            acc += __shfl_xor_sync(0xFFFFFFFFu, acc, o);
        // acc >= 0 -> IEEE bits order-preserving; low 32 = index, so u64 min
        // ties break to the SMALLEST index (jnp.argmin first-min semantics).
        packed = ((unsigned long long)__float_as_uint(acc) << 32) | (unsigned)cand;
    }

    if (lane == 0) s_best[warp] = packed;
    __syncthreads();

    if (tid == 0) {
        unsigned long long b = s_best[0];
        #pragma unroll
        for (int w = 1; w < WARPS_PER_BLOCK; w++) b = min(b, s_best[w]);
        atomicMin(&g_best, b);
    }
    // Signal PDL: this block's contribution to g_best is committed.
    cudaTriggerProgrammaticLaunchCompletion();
}

// Launched with programmatic dependency: resident during the dist kernel,
// proceeds the instant all dist blocks have triggered (atomicMins visible
// per the PDL memory-visibility contract).
__global__ void nn_gather_kernel(const float* __restrict__ target_vels,
                                 float* __restrict__ out)
{
    cudaGridDependencySynchronize();

    __shared__ unsigned int s_bestidx;
    if (threadIdx.x == 0)
        s_bestidx = (unsigned)(g_best & 0xFFFFFFFFULL);
    __syncthreads();

    const float4* src = reinterpret_cast<const float4*>(target_vels)
                        + (size_t)s_bestidx * OUT_F4;
    float4* dst = reinterpret_cast<float4*>(out);
    for (int i = threadIdx.x; i < OUT_F4; i += blockDim.x)
        dst[i] = src[i];

    __syncthreads();
    if (threadIdx.x == 0)
        g_best = 0xFFFFFFFFFFFFFFFFULL;   // clean state for next replay
}

extern "C" void kernel_launch(void* const* d_in, const int* in_sizes, int n_in,
                              void* d_out, int out_size)
{
    const float* in_pose     = (const float*)d_in[0];   // [16, 96]
    const float* train_poses = (const float*)d_in[1];   // [N, 16, 96]
    const float* target_vels = (const float*)d_in[2];   // [N, 25, 96]
    float* out = (float*)d_out;                          // [25, 96]

    const int N = in_sizes[1] / ROW_F;
    const int blocks = (N + WARPS_PER_BLOCK - 1) / WARPS_PER_BLOCK;

    nn_dist_kernel<<<blocks, 256>>>(in_pose, train_poses, N);

    // Gather with programmatic dependent launch: overlaps launch/prologue
    // with the dist kernel; self-synchronizes via gridDependencySynchronize.
    cudaLaunchAttribute attrs[1];
    attrs[0].id = cudaLaunchAttributeProgrammaticStreamSerialization;
    attrs[0].val.programmaticStreamSerializationAllowed = 1;

    cudaLaunchConfig_t cfg = {};
    cfg.gridDim  = dim3(1, 1, 1);
    cfg.blockDim = dim3(256, 1, 1);
    cfg.dynamicSmemBytes = 0;
    cfg.stream = 0;
    cfg.attrs = attrs;
    cfg.numAttrs = 1;

    cudaLaunchKernelEx(&cfg, nn_gather_kernel, target_vels, out);
}

// round 17
// speedup vs baseline: 1.0177x; 1.0162x over previous
#include <cuda_runtime.h>
#include <cstdint>

// N=100000 candidates, OBS=16, FEAT=96 -> ROW=1536 floats per candidate.
// target_vels row = 25*96 = 2400 floats.
#define ROW_F       1536
#define ROW_F4      (ROW_F / 4)       // 384 float4
#define F4_PER_LANE (ROW_F4 / 32)     // 12
#define OUT_F       2400
#define OUT_F4      (OUT_F / 4)       // 600
#define WARPS_PER_BLOCK 8
#define NSLOTS      16
#define SLOT_STRIDE 16                // 16 u64 = 128 B apart: distinct L2 lines

// Striped best-slots: 16-way lower same-address atomic contention at the
// end-of-kernel commit burst. Statically initialized for the first
// (uncaptured) correctness call; the gather kernel resets all slots after
// use, so every graph replay starts clean.
__device__ unsigned long long g_best[NSLOTS * SLOT_STRIDE] = {
    0xFFFFFFFFFFFFFFFFULL, 0, 0, 0, 0, 0, 0, 0, 0, 0, 0, 0, 0, 0, 0, 0,
    0xFFFFFFFFFFFFFFFFULL, 0, 0, 0, 0, 0, 0, 0, 0, 0, 0, 0, 0, 0, 0, 0,
    0xFFFFFFFFFFFFFFFFULL, 0, 0, 0, 0, 0, 0, 0, 0, 0, 0, 0, 0, 0, 0, 0,
    0xFFFFFFFFFFFFFFFFULL, 0, 0, 0, 0, 0, 0, 0, 0, 0, 0, 0, 0, 0, 0, 0,
    0xFFFFFFFFFFFFFFFFULL, 0, 0, 0, 0, 0, 0, 0, 0, 0, 0, 0, 0, 0, 0, 0,
    0xFFFFFFFFFFFFFFFFULL, 0, 0, 0, 0, 0, 0, 0, 0, 0, 0, 0, 0, 0, 0, 0,
    0xFFFFFFFFFFFFFFFFULL, 0, 0, 0, 0, 0, 0, 0, 0, 0, 0, 0, 0, 0, 0, 0,
    0xFFFFFFFFFFFFFFFFULL, 0, 0, 0, 0, 0, 0, 0, 0, 0, 0, 0, 0, 0, 0, 0,
    0xFFFFFFFFFFFFFFFFULL, 0, 0, 0, 0, 0, 0, 0, 0, 0, 0, 0, 0, 0, 0, 0,
    0xFFFFFFFFFFFFFFFFULL, 0, 0, 0, 0, 0, 0, 0, 0, 0, 0, 0, 0, 0, 0, 0,
    0xFFFFFFFFFFFFFFFFULL, 0, 0, 0, 0, 0, 0, 0, 0, 0, 0, 0, 0, 0, 0, 0,
    0xFFFFFFFFFFFFFFFFULL, 0, 0, 0, 0, 0, 0, 0, 0, 0, 0, 0, 0, 0, 0, 0,
    0xFFFFFFFFFFFFFFFFULL, 0, 0, 0, 0, 0, 0, 0, 0, 0, 0, 0, 0, 0, 0, 0,
    0xFFFFFFFFFFFFFFFFULL, 0, 0, 0, 0, 0, 0, 0, 0, 0, 0, 0, 0, 0, 0, 0,
    0xFFFFFFFFFFFFFFFFULL, 0, 0, 0, 0, 0, 0, 0, 0, 0, 0, 0, 0, 0, 0, 0,
    0xFFFFFFFFFFFFFFFFULL, 0, 0, 0, 0, 0, 0, 0, 0, 0, 0, 0, 0, 0, 0, 0
};

// Converged floor config: one warp per candidate, 8 warps/block, shared-
// staged query (one LDG + one LDS per iter), 32 regs, ~97% occupancy; the
// 614 MB stream runs at the ~6.9 TB/s HBM read ceiling. Only change vs the
// 90.62 bank: atomicMin striped over 16 slots (tail-contention relief).
__global__ __launch_bounds__(256, 8) void nn_dist_kernel(
    const float* __restrict__ in_pose,
    const float* __restrict__ train,
    int N)
{
    __shared__ float4 s_q[ROW_F4];
    __shared__ unsigned long long s_best[WARPS_PER_BLOCK];

    const int tid  = threadIdx.x;
    const int warp = tid >> 5;
    const int lane = tid & 31;

    // stage query (6 KB) into shared
    for (int i = tid; i < ROW_F4; i += blockDim.x)
        s_q[i] = reinterpret_cast<const float4*>(in_pose)[i];
    __syncthreads();

    const int cand = blockIdx.x * WARPS_PER_BLOCK + warp;
    unsigned long long packed = 0xFFFFFFFFFFFFFFFFULL;

    if (cand < N) {
        const float4* row = reinterpret_cast<const float4*>(train) + (size_t)cand * ROW_F4;
        float acc = 0.f;
        #pragma unroll
        for (int j = 0; j < F4_PER_LANE; j++) {
            const int idx = j * 32 + lane;
            float4 a = row[idx];
            float4 q = s_q[idx];
            float dx = a.x - q.x;
            float dy = a.y - q.y;
            float dz = a.z - q.z;
            float dw = a.w - q.w;
            acc += dx * dx + dy * dy + dz * dz + dw * dw;
        }
        #pragma unroll
        for (int o = 16; o > 0; o >>= 1)
            acc += __shfl_xor_sync(0xFFFFFFFFu, acc, o);
        // acc >= 0 -> IEEE bits order-preserving; low 32 = index, so u64 min
        // ties break to the SMALLEST index (jnp.argmin first-min semantics).
        packed = ((unsigned long long)__float_as_uint(acc) << 32) | (unsigned)cand;
    }

    if (lane == 0) s_best[warp] = packed;
    __syncthreads();

    if (tid == 0) {
        unsigned long long b = s_best[0];
        #pragma unroll
        for (int w = 1; w < WARPS_PER_BLOCK; w++) b = min(b, s_best[w]);
        atomicMin(&g_best[(blockIdx.x & (NSLOTS - 1)) * SLOT_STRIDE], b);
    }
    // Signal PDL: this block's contribution is committed.
    cudaTriggerProgrammaticLaunchCompletion();
}

// PDL gather: resident during the dist kernel, proceeds the instant all dist
// blocks have triggered (atomicMins visible per the PDL contract). Reduces
// the 16 slots, copies the winning row, then resets all slots.
__global__ void nn_gather_kernel(const float* __restrict__ target_vels,
                                 float* __restrict__ out)
{
    cudaGridDependencySynchronize();

    __shared__ unsigned int s_bestidx;
    if (threadIdx.x == 0) {
        unsigned long long b = g_best[0];
        #pragma unroll
        for (int s = 1; s < NSLOTS; s++)
            b = min(b, g_best[s * SLOT_STRIDE]);
        s_bestidx = (unsigned)(b & 0xFFFFFFFFULL);
    }
    __syncthreads();

    const float4* src = reinterpret_cast<const float4*>(target_vels)
                        + (size_t)s_bestidx * OUT_F4;
    float4* dst = reinterpret_cast<float4*>(out);
    for (int i = threadIdx.x; i < OUT_F4; i += blockDim.x)
        dst[i] = src[i];

    __syncthreads();
    if (threadIdx.x < NSLOTS)   // clean all slots for the next replay
        g_best[threadIdx.x * SLOT_STRIDE] = 0xFFFFFFFFFFFFFFFFULL;
}

extern "C" void kernel_launch(void* const* d_in, const int* in_sizes, int n_in,
                              void* d_out, int out_size)
{
    const float* in_pose     = (const float*)d_in[0];   // [16, 96]
    const float* train_poses = (const float*)d_in[1];   // [N, 16, 96]
    const float* target_vels = (const float*)d_in[2];   // [N, 25, 96]
    float* out = (float*)d_out;                          // [25, 96]

    const int N = in_sizes[1] / ROW_F;
    const int blocks = (N + WARPS_PER_BLOCK - 1) / WARPS_PER_BLOCK;

    nn_dist_kernel<<<blocks, 256>>>(in_pose, train_poses, N);

    // Gather with programmatic dependent launch: overlaps launch/prologue
    // with the dist kernel; self-synchronizes via gridDependencySynchronize.
    cudaLaunchAttribute attrs[1];
    attrs[0].id = cudaLaunchAttributeProgrammaticStreamSerialization;
    attrs[0].val.programmaticStreamSerializationAllowed = 1;

    cudaLaunchConfig_t cfg = {};
    cfg.gridDim  = dim3(1, 1, 1);
    cfg.blockDim = dim3(256, 1, 1);
    cfg.dynamicSmemBytes = 0;
    cfg.stream = 0;
    cfg.attrs = attrs;
    cfg.numAttrs = 1;

    cudaLaunchKernelEx(&cfg, nn_gather_kernel, target_vels, out);
}